// round 1
// baseline (speedup 1.0000x reference)
#include <cuda_runtime.h>

// out = x + delta for the NVM shift op.
// Row layout (D=512):
//   col 0: OP_SHL flag, col 1: OP_SHR flag, col 2: MARK_AX flag
//   cols 16-31 : ALU_LO   (argmax -> a_lo)
//   cols 32-47 : ALU_HI   (argmax -> a_hi)
//   cols 48-63 : AX_CARRY_LO (argmax -> shift, clipped to [0,7])
//   cols 64-79 : OUTPUT_LO (add active at 64 + r_lo)
//   cols 80-95 : OUTPUT_HI (add active at 80 + r_hi)
// a = a_lo + 16*a_hi; result = active_shl ? (a<<s)&255 : a>>s (integer-exact
// vs the reference's fp32 magic-floor formulation for these ranges).
//
// One 128-thread block per row; thread t owns float4 covering cols 4t..4t+3.
// All decode + delta lanes fall in cols 0..127 => warp 0 only. Warps 1-3 copy.

__global__ __launch_bounds__(128) void shift_kernel(const float* __restrict__ x,
                                                    float* __restrict__ out) {
    const long long row = blockIdx.x;
    const int t = threadIdx.x;                 // 0..127
    const float4* __restrict__ xin = reinterpret_cast<const float4*>(x) + row * 128;
    float4* __restrict__ xout = reinterpret_cast<float4*>(out) + row * 128;

    float4 v = xin[t];

    if (t < 32) {
        const int lane = t;

        // ---- per-lane local argmax over its 4 elements, for the 3 fields ----
        // lanes 4-7  -> ALU_LO (cols 16-31), local idx base (lane-4)*4
        // lanes 8-11 -> ALU_HI (cols 32-47)
        // lanes 12-15-> AX_CARRY_LO (cols 48-63)
        float m = -1e30f;
        int mi = 0x7fffffff;
        if (lane >= 4 && lane < 16) {
            const int base = (lane & 3) * 4;   // (lane - fieldStart)*4 since fieldStart%4==0
            float vals[4] = {v.x, v.y, v.z, v.w};
            m = vals[0];
            mi = base;
            #pragma unroll
            for (int j = 1; j < 4; j++) {
                if (vals[j] > m) { m = vals[j]; mi = base + j; }
            }
        }
        // group-of-4 max reduction (first-max-wins tie-break, matching jnp.argmax)
        #pragma unroll
        for (int off = 1; off <= 2; off <<= 1) {
            float om = __shfl_xor_sync(0xffffffffu, m, off);
            int omi = __shfl_xor_sync(0xffffffffu, mi, off);
            if (om > m || (om == m && omi < mi)) { m = om; mi = omi; }
        }
        const int a_lo = __shfl_sync(0xffffffffu, mi, 4);
        const int a_hi = __shfl_sync(0xffffffffu, mi, 8);
        int shift     = __shfl_sync(0xffffffffu, mi, 12);

        // ---- flags from lane 0 (cols 0,1,2 = v.x,v.y,v.z) ----
        int flags = 0;
        if (lane == 0) {
            flags = (v.x > 0.5f ? 1 : 0) | (v.y > 0.5f ? 2 : 0) | (v.z > 0.5f ? 4 : 0);
        }
        flags = __shfl_sync(0xffffffffu, flags, 0);

        const bool mark = (flags & 4) != 0;
        const bool active_shl = ((flags & 1) != 0) && mark;
        const bool active_shr = ((flags & 2) != 0) && mark;
        const bool active = active_shl || active_shr;

        if (active) {
            if (shift > 7) shift = 7;
            const int a = a_lo + (a_hi << 4);                       // [0,255]
            const int result = active_shl ? ((a << shift) & 255)
                                          : (a >> shift);
            const int col_lo = 64 + (result & 15);
            const int col_hi = 80 + ((result >> 4) & 15);

            // lanes 16-23 own cols 64..95; add 1.0f in-register before store
            const int myc = lane << 2;
            float* vf = reinterpret_cast<float*>(&v);
            if ((unsigned)(col_lo - myc) < 4u) vf[col_lo - myc] += 1.0f;
            if ((unsigned)(col_hi - myc) < 4u) vf[col_hi - myc] += 1.0f;
        }
    }

    xout[t] = v;
}

extern "C" void kernel_launch(void* const* d_in, const int* in_sizes, int n_in,
                              void* d_out, int out_size) {
    const float* x = (const float*)d_in[0];
    float* out = (float*)d_out;
    const int rows = in_sizes[0] / 512;        // 262144
    shift_kernel<<<rows, 128>>>(x, out);
}